// round 15
// baseline (speedup 1.0000x reference)
#include <cuda_runtime.h>

#define B 32
#define T 1024
#define D 384
#define T_OUT 4096
#define F4_PER_ROW (D / 4)        // 96
#define ROWS_PER_THREAD 8
#define ROW_LANES 4               // 384 / 96
#define ROWS_PER_BLOCK (ROW_LANES * ROWS_PER_THREAD)   // 32
#define BLOCKS_PER_BATCH (T_OUT / ROWS_PER_BLOCK)      // 128
#define SCAN_THREADS 256          // each scans 4 contiguous durations (int4)

// ---------------------------------------------------------------------------
// Fused LengthRegulator kernel — CONVERGED configuration.
//
// Structure: per-block recompute of the batch's duration cumsum (4 KB,
// L2-broadcast across the 128 blocks of each batch), searchsorted for this
// block's 32 output rows, then an ILP=8 float4 gather with streaming stores.
//
// Measured facts driving this shape (GB300, sm_103a):
//  - Kernel is pinned at the chip memory ceiling: 251 MB compulsory traffic
//    (201 MB out + 50 MB in) at ~6.4 TB/s effective ≈ 39.3-40.1 us across
//    every structural variant tried (ILP 8/16, grid 2048/4096, plain/stcs).
//  - Occupancy (TLP) is the feed mechanism, NOT per-thread MLP: forcing all
//    8 loads live via a register barrier (regs 32->48, occ 81->50%) cost +50%
//    time (R12). ptxas's ld/st software pipelining at regs=32 is the fast
//    schedule — leave it alone.
//  - Fusing the scan into the gather kernel (vs a separate index kernel)
//    removed a 7 us serial prologue (R8).
//
// grid = B * BLOCKS_PER_BATCH = 4096, block = 384
// ---------------------------------------------------------------------------
__global__ __launch_bounds__(384) void fused_kernel(
    const float4* __restrict__ x,        // [B, T, 96] as float4
    const int4*   __restrict__ dur4,     // [B, T/4] as int4
    const int*    __restrict__ target_len,
    float4*       __restrict__ out)      // [B, T_OUT, 96] as float4
{
    __shared__ int s_ends[T + 1];        // inclusive cumsum + sentinel
    __shared__ int s_warp[SCAN_THREADS / 32];   // 8 warp sums
    __shared__ int s_idx[ROWS_PER_BLOCK];       // idx per row, -1 = zeros

    const int tid   = threadIdx.x;
    const int b     = blockIdx.x / BLOCKS_PER_BATCH;
    const int chunk = blockIdx.x - b * BLOCKS_PER_BATCH;

    // ---- 1) block-local scan of this batch's durations (first 256 threads)
    if (tid < SCAN_THREADS) {
        const int lane = tid & 31;
        const int wid  = tid >> 5;

        int4 d = __ldg(&dur4[b * (T / 4) + tid]);
        int e0 = d.x < 0 ? 0 : d.x;
        int e1 = d.y < 0 ? 0 : d.y;
        int e2 = d.z < 0 ? 0 : d.z;
        int e3 = d.w < 0 ? 0 : d.w;
        // local inclusive prefix over the 4
        int p0 = e0, p1 = p0 + e1, p2 = p1 + e2, p3 = p2 + e3;

        // warp inclusive scan of the per-thread sums (p3)
        int ws = p3;
        #pragma unroll
        for (int off = 1; off < 32; off <<= 1) {
            int n = __shfl_up_sync(0xFFFFFFFFu, ws, off);
            if (lane >= off) ws += n;
        }
        if (lane == 31) s_warp[wid] = ws;
        __syncthreads();

        // scan the 8 warp sums (warp 0, lanes 0..7)
        if (wid == 0 && lane < 8) {
            int w = s_warp[lane];
            #pragma unroll
            for (int off = 1; off < 8; off <<= 1) {
                int n = __shfl_up_sync(0xFFu, w, off);
                if (lane >= off) w += n;
            }
            s_warp[lane] = w;
        }
        __syncthreads();

        const int warp_off = (wid > 0) ? s_warp[wid - 1] : 0;
        const int base = warp_off + (ws - p3);   // exclusive prefix for this thread
        s_ends[4 * tid + 0] = base + p0;
        s_ends[4 * tid + 1] = base + p1;
        s_ends[4 * tid + 2] = base + p2;
        s_ends[4 * tid + 3] = base + p3;
        if (tid == 0) s_ends[T] = 0x7FFFFFFF;    // sentinel
    } else {
        __syncthreads();
        __syncthreads();
    }
    __syncthreads();

    // ---- 2) searchsorted for this block's 32 output positions
    if (tid < ROWS_PER_BLOCK) {
        const int pos   = chunk * ROWS_PER_BLOCK + tid;
        const int total = s_ends[T - 1];
        const int tl    = __ldg(&target_len[b]);
        const int limit = total < tl ? total : tl;

        // first i with ends[i] > pos; answer space {0..T} -> 11 iterations
        int lo = 0, hi = T;
        #pragma unroll
        for (int it = 0; it < 11; it++) {
            int mid = (lo + hi) >> 1;
            if (s_ends[mid] <= pos) lo = mid + 1; else hi = mid;
        }
        int idx = lo < (T - 1) ? lo : (T - 1);
        s_idx[tid] = (pos < limit) ? idx : -1;
    }
    __syncthreads();

    // ---- 3) ILP=8 gather, float4-vectorized, coalesced streaming stores
    const int rsub = tid / F4_PER_ROW;           // 0..3
    const int c    = tid - rsub * F4_PER_ROW;    // 0..95
    const long row_base = (long)b * T_OUT + chunk * ROWS_PER_BLOCK;

    int idxs[ROWS_PER_THREAD];
    #pragma unroll
    for (int k = 0; k < ROWS_PER_THREAD; k++) {
        idxs[k] = s_idx[rsub + k * ROW_LANES];
    }

    float4 vals[ROWS_PER_THREAD];
    #pragma unroll
    for (int k = 0; k < ROWS_PER_THREAD; k++) {
        const int idx = idxs[k];
        if (idx >= 0) {
            vals[k] = __ldg(&x[((long)b * T + idx) * F4_PER_ROW + c]);
        } else {
            vals[k] = make_float4(0.f, 0.f, 0.f, 0.f);
        }
    }

    #pragma unroll
    for (int k = 0; k < ROWS_PER_THREAD; k++) {
        // streaming store: output is never re-read; keep L2 for x reuse
        __stcs(&out[(row_base + rsub + k * ROW_LANES) * F4_PER_ROW + c], vals[k]);
    }
}

// ---------------------------------------------------------------------------
extern "C" void kernel_launch(void* const* d_in, const int* in_sizes, int n_in,
                              void* d_out, int out_size)
{
    const float* x          = (const float*)d_in[0];
    const int*   durations  = (const int*)d_in[1];
    const int*   target_len = (const int*)d_in[2];
    float*       out        = (float*)d_out;

    fused_kernel<<<B * BLOCKS_PER_BATCH, 384>>>(
        (const float4*)x, (const int4*)durations, target_len, (float4*)out);
}

// round 16
// speedup vs baseline: 1.0162x; 1.0162x over previous
#include <cuda_runtime.h>

#define B 32
#define T 1024
#define D 384
#define T_OUT 4096
#define F4_PER_ROW (D / 4)        // 96
#define ROWS_PER_THREAD 8
#define ROW_LANES 4               // 384 / 96
#define ROWS_PER_BLOCK (ROW_LANES * ROWS_PER_THREAD)   // 32
#define BLOCKS_PER_BATCH (T_OUT / ROWS_PER_BLOCK)      // 128
#define SCAN_THREADS 256          // each scans 4 contiguous durations (int4)

// ---------------------------------------------------------------------------
// Fused LengthRegulator kernel — FINAL converged configuration.
//
// Structure: per-block recompute of the batch's duration cumsum (4 KB,
// L2-broadcast across the 128 blocks of each batch), searchsorted for this
// block's 32 output rows, then an ILP=8 float4 gather with streaming stores.
//
// Measured facts (GB300, sm_103a) that fix this shape:
//  - Pinned at the chip memory ceiling: 251 MB compulsory traffic
//    (201 MB out + 50 MB in) at ~6.35 TB/s effective = 39.3-40.1 us kernel
//    across every structural variant (ILP 8/16, grid 2048/4096, plain/stcs).
//    TMA and LDG share the same LTS cap, so no rewrite moves this.
//  - Occupancy (TLP) feeds the memory system, NOT per-thread MLP: forcing
//    all 8 loads live via a register barrier (regs 32->48, occ 81->50%)
//    regressed +50% (R12). ptxas's ld/st software pipelining at regs=32 is
//    the fast schedule — leave it alone.
//  - Fusing the scan into the gather kernel removed a 7 us serial prologue.
//
// grid = B * BLOCKS_PER_BATCH = 4096, block = 384
// ---------------------------------------------------------------------------
__global__ __launch_bounds__(384) void fused_kernel(
    const float4* __restrict__ x,        // [B, T, 96] as float4
    const int4*   __restrict__ dur4,     // [B, T/4] as int4
    const int*    __restrict__ target_len,
    float4*       __restrict__ out)      // [B, T_OUT, 96] as float4
{
    __shared__ int s_ends[T + 1];        // inclusive cumsum + sentinel
    __shared__ int s_warp[SCAN_THREADS / 32];   // 8 warp sums
    __shared__ int s_idx[ROWS_PER_BLOCK];       // idx per row, -1 = zeros

    const int tid   = threadIdx.x;
    const int b     = blockIdx.x / BLOCKS_PER_BATCH;
    const int chunk = blockIdx.x - b * BLOCKS_PER_BATCH;

    // ---- 1) block-local scan of this batch's durations (first 256 threads)
    if (tid < SCAN_THREADS) {
        const int lane = tid & 31;
        const int wid  = tid >> 5;

        int4 d = __ldg(&dur4[b * (T / 4) + tid]);
        int e0 = d.x < 0 ? 0 : d.x;
        int e1 = d.y < 0 ? 0 : d.y;
        int e2 = d.z < 0 ? 0 : d.z;
        int e3 = d.w < 0 ? 0 : d.w;
        // local inclusive prefix over the 4
        int p0 = e0, p1 = p0 + e1, p2 = p1 + e2, p3 = p2 + e3;

        // warp inclusive scan of the per-thread sums (p3)
        int ws = p3;
        #pragma unroll
        for (int off = 1; off < 32; off <<= 1) {
            int n = __shfl_up_sync(0xFFFFFFFFu, ws, off);
            if (lane >= off) ws += n;
        }
        if (lane == 31) s_warp[wid] = ws;
        __syncthreads();

        // scan the 8 warp sums (warp 0, lanes 0..7)
        if (wid == 0 && lane < 8) {
            int w = s_warp[lane];
            #pragma unroll
            for (int off = 1; off < 8; off <<= 1) {
                int n = __shfl_up_sync(0xFFu, w, off);
                if (lane >= off) w += n;
            }
            s_warp[lane] = w;
        }
        __syncthreads();

        const int warp_off = (wid > 0) ? s_warp[wid - 1] : 0;
        const int base = warp_off + (ws - p3);   // exclusive prefix for this thread
        s_ends[4 * tid + 0] = base + p0;
        s_ends[4 * tid + 1] = base + p1;
        s_ends[4 * tid + 2] = base + p2;
        s_ends[4 * tid + 3] = base + p3;
        if (tid == 0) s_ends[T] = 0x7FFFFFFF;    // sentinel
    } else {
        __syncthreads();
        __syncthreads();
    }
    __syncthreads();

    // ---- 2) searchsorted for this block's 32 output positions
    if (tid < ROWS_PER_BLOCK) {
        const int pos   = chunk * ROWS_PER_BLOCK + tid;
        const int total = s_ends[T - 1];
        const int tl    = __ldg(&target_len[b]);
        const int limit = total < tl ? total : tl;

        // first i with ends[i] > pos; answer space {0..T} -> 11 iterations
        int lo = 0, hi = T;
        #pragma unroll
        for (int it = 0; it < 11; it++) {
            int mid = (lo + hi) >> 1;
            if (s_ends[mid] <= pos) lo = mid + 1; else hi = mid;
        }
        int idx = lo < (T - 1) ? lo : (T - 1);
        s_idx[tid] = (pos < limit) ? idx : -1;
    }
    __syncthreads();

    // ---- 3) ILP=8 gather, float4-vectorized, coalesced streaming stores
    const int rsub = tid / F4_PER_ROW;           // 0..3
    const int c    = tid - rsub * F4_PER_ROW;    // 0..95
    const long row_base = (long)b * T_OUT + chunk * ROWS_PER_BLOCK;

    int idxs[ROWS_PER_THREAD];
    #pragma unroll
    for (int k = 0; k < ROWS_PER_THREAD; k++) {
        idxs[k] = s_idx[rsub + k * ROW_LANES];
    }

    float4 vals[ROWS_PER_THREAD];
    #pragma unroll
    for (int k = 0; k < ROWS_PER_THREAD; k++) {
        const int idx = idxs[k];
        if (idx >= 0) {
            vals[k] = __ldg(&x[((long)b * T + idx) * F4_PER_ROW + c]);
        } else {
            vals[k] = make_float4(0.f, 0.f, 0.f, 0.f);
        }
    }

    #pragma unroll
    for (int k = 0; k < ROWS_PER_THREAD; k++) {
        // streaming store: output is never re-read; keep L2 for x reuse
        __stcs(&out[(row_base + rsub + k * ROW_LANES) * F4_PER_ROW + c], vals[k]);
    }
}

// ---------------------------------------------------------------------------
extern "C" void kernel_launch(void* const* d_in, const int* in_sizes, int n_in,
                              void* d_out, int out_size)
{
    const float* x          = (const float*)d_in[0];
    const int*   durations  = (const int*)d_in[1];
    const int*   target_len = (const int*)d_in[2];
    float*       out        = (float*)d_out;

    fused_kernel<<<B * BLOCKS_PER_BATCH, 384>>>(
        (const float4*)x, (const int4*)durations, target_len, (float4*)out);
}